// round 1
// baseline (speedup 1.0000x reference)
#include <cuda_runtime.h>

// LMNN loss on GB300.
// outputs: [2048, 512, 128] f32, label_inds: [2048, 511] i32, out: scalar f32.
//
// One CTA per segment. Warp-per-point: lane l holds float4 of dims [4l, 4l+4),
// so each point row (512 B) is one fully-coalesced LDG.128 per lane.
// d2[j] cached in SMEM; then min-over-same and hinge-sum passes; one
// atomicAdd per segment into the scalar output.

#define NSEG 2048
#define PPS  512
#define DDIM 128
#define NPTS 511   // PPS - 1

__global__ void lmnn_init_out(float* out) { *out = 0.0f; }

__global__ __launch_bounds__(256, 8)
void lmnn_kernel(const float* __restrict__ outputs,
                 const int*   __restrict__ labels,
                 float*       __restrict__ out)
{
    __shared__ float sh_d2[NPTS];
    __shared__ int   sh_same[NPTS];
    __shared__ float sh_red[8];

    const int seg  = blockIdx.x;
    const int tid  = threadIdx.x;
    const int warp = tid >> 5;
    const int lane = tid & 31;

    // Row base for this segment, viewed as float4 (32 float4 per 128-f row).
    const float4* base = reinterpret_cast<const float4*>(
        outputs + (size_t)seg * PPS * DDIM);

    // Center row: lane l owns dims [4l, 4l+4). Redundant per-warp load; L1 hit.
    const float4 c = base[lane];

    // Same-label flags (vs label of point 0 of the 511).
    const int* lab = labels + (size_t)seg * NPTS;
    const int lab0 = lab[0];
    for (int j = tid; j < NPTS; j += 256)
        sh_same[j] = (lab[j] == lab0);

    // d2 for each point: warp w handles points w, w+8, w+16, ...
    #pragma unroll 4
    for (int j = warp; j < NPTS; j += 8) {
        const float4 p = base[(j + 1) * (DDIM / 4) + lane];
        const float dx = p.x - c.x;
        const float dy = p.y - c.y;
        const float dz = p.z - c.z;
        const float dw = p.w - c.w;
        float s = dx * dx + dy * dy + dz * dz + dw * dw;
        #pragma unroll
        for (int o = 16; o > 0; o >>= 1)
            s += __shfl_xor_sync(0xffffffffu, s, o);
        if (lane == 0) sh_d2[j] = s;
    }
    __syncthreads();

    // pull_d = min d2 over same-label points (j=0 is always same, so nonempty).
    float lmin = __int_as_float(0x7f800000);  // +inf
    for (int j = tid; j < NPTS; j += 256)
        if (sh_same[j]) lmin = fminf(lmin, sh_d2[j]);
    #pragma unroll
    for (int o = 16; o > 0; o >>= 1)
        lmin = fminf(lmin, __shfl_xor_sync(0xffffffffu, lmin, o));
    if (lane == 0) sh_red[warp] = lmin;
    __syncthreads();

    float pull = sh_red[0];
    #pragma unroll
    for (int w = 1; w < 8; w++) pull = fminf(pull, sh_red[w]);
    const float margin = 1.0f + pull;

    // push = sum over diff-label points of max(margin - d2, 0).
    float lsum = 0.0f;
    for (int j = tid; j < NPTS; j += 256)
        if (!sh_same[j]) lsum += fmaxf(margin - sh_d2[j], 0.0f);
    #pragma unroll
    for (int o = 16; o > 0; o >>= 1)
        lsum += __shfl_xor_sync(0xffffffffu, lsum, o);
    __syncthreads();          // all reads of sh_red (pull) done before reuse
    if (lane == 0) sh_red[warp] = lsum;
    __syncthreads();

    if (tid == 0) {
        float push = 0.0f;
        #pragma unroll
        for (int w = 0; w < 8; w++) push += sh_red[w];
        const float inv_n = 1.0f / (float)((size_t)NSEG * PPS);
        atomicAdd(out, (pull + push) * inv_n);
    }
}

extern "C" void kernel_launch(void* const* d_in, const int* in_sizes, int n_in,
                              void* d_out, int out_size)
{
    const float* outputs = (const float*)d_in[0];
    const int*   labels  = (const int*)d_in[1];
    float*       out     = (float*)d_out;

    lmnn_init_out<<<1, 1>>>(out);
    lmnn_kernel<<<NSEG, 256>>>(outputs, labels, out);
}